// round 4
// baseline (speedup 1.0000x reference)
#include <cuda_runtime.h>
#include <cuda_fp16.h>

#define N_NODES 50000
#define N_EDGES 800000
#define IN_C    16
#define OUT_C   16
#define EDGE_F  8

// y table in fp16: per node 9 blocks (8 edge-feature + 1 bias) x 16 outputs,
// = 18 uint4, PADDED to 24 uint4 (384 B = 3 cache lines, 128B-aligned) so an
// 8-lane cooperative gather reads whole aligned lines.
// index = n*24 + f*2 + h   (h = output half, uint4 units)
#define YSTRIDE 24

__device__ __align__(128) uint4 g_yh[N_NODES * YSTRIDE];   // 19.2 MB

#define EDGE_BLOCKS (N_EDGES / 32)     // 256 thr = 32 edges/block -> 25000
#define ECHO_BLOCKS 2048

// ---------------------------------------------------------------------------
// Kernel A: per-node precompute (fp16 y table, fp32 root-term init of out).
// ---------------------------------------------------------------------------
__global__ void node_kernel(const float* __restrict__ x,
                            const float* __restrict__ w_nn,
                            const float* __restrict__ b_nn,
                            const float* __restrict__ root,
                            const float* __restrict__ bias,
                            float* __restrict__ out)
{
    __shared__ float Wsh[9 * 256];      // [f][i*16+o], f==8 holds b_nn
    __shared__ float Rsh[256 + 16];     // root [i][o] + bias[o]

    for (int t = threadIdx.x; t < 2048; t += blockDim.x) Wsh[t] = w_nn[t];
    for (int t = threadIdx.x; t < 256;  t += blockDim.x) Wsh[2048 + t] = b_nn[t];
    for (int t = threadIdx.x; t < 256;  t += blockDim.x) Rsh[t] = root[t];
    for (int t = threadIdx.x; t < 16;   t += blockDim.x) Rsh[256 + t] = bias[t];
    __syncthreads();

    const int gsz  = gridDim.x * blockDim.x;
    const int tid0 = blockIdx.x * blockDim.x + threadIdx.x;

    // ---- y precompute: thread = (node, output-half). 9 f-blocks each. ----
    for (int t = tid0; t < N_NODES * 2; t += gsz) {
        int n = t >> 1;
        int h = t & 1;                 // outputs h*8 .. h*8+7

        const float4* xr = (const float4*)(x + n * IN_C);
        float xv[16];
        #pragma unroll
        for (int ii = 0; ii < 4; ii++) {
            float4 xx = xr[ii];
            xv[4*ii+0] = xx.x; xv[4*ii+1] = xx.y; xv[4*ii+2] = xx.z; xv[4*ii+3] = xx.w;
        }

        #pragma unroll
        for (int f = 0; f < 9; f++) {
            const float* wb = &Wsh[f * 256 + h * 8];
            float acc[8];
            #pragma unroll
            for (int o = 0; o < 8; o++) acc[o] = 0.f;
            #pragma unroll
            for (int i = 0; i < 16; i++) {
                float xi = xv[i];
                #pragma unroll
                for (int o = 0; o < 8; o++) acc[o] += xi * wb[i * 16 + o];
            }
            __half2 hv[4];
            #pragma unroll
            for (int j = 0; j < 4; j++)
                hv[j] = __floats2half2_rn(acc[2*j], acc[2*j+1]);
            g_yh[n * YSTRIDE + f * 2 + h] = *(const uint4*)hv;
        }
    }

    // ---- root term init: out[n][oq*4..+3] = bias + x[n] @ root ----
    for (int t = tid0; t < N_NODES * 4; t += gsz) {
        int n  = t >> 2;
        int oq = t & 3;

        const float4* xr = (const float4*)(x + n * IN_C);
        float xv[16];
        #pragma unroll
        for (int ii = 0; ii < 4; ii++) {
            float4 xx = xr[ii];
            xv[4*ii+0] = xx.x; xv[4*ii+1] = xx.y; xv[4*ii+2] = xx.z; xv[4*ii+3] = xx.w;
        }

        float4 acc = *(const float4*)&Rsh[256 + oq * 4];
        #pragma unroll
        for (int i = 0; i < 16; i++) {
            float xi = xv[i];
            const float4 r = *(const float4*)&Rsh[i * 16 + oq * 4];
            acc.x += xi * r.x; acc.y += xi * r.y; acc.z += xi * r.z; acc.w += xi * r.w;
        }
        ((float4*)out)[t] = acc;
    }
}

// ---------------------------------------------------------------------------
// Kernel B: 8 lanes per edge. Cooperative line-granular gather of the 384 B
// padded y row (3 aligned LDG.128 wavefronts/edge), shfl_xor reduction,
// 4-lane red.v4 scatter (1 wavefront/edge). Extra blocks stream the echoes.
// ---------------------------------------------------------------------------
__global__ void edge_kernel(const int*   __restrict__ ei,
                            const float* __restrict__ ea,
                            float* __restrict__ out)
{
    if (blockIdx.x >= EDGE_BLOCKS) {
        // ---- echo blocks: pure DRAM streaming, overlaps the L1-bound work ----
        const int gsz  = ECHO_BLOCKS * 256;
        const int tid0 = (blockIdx.x - EDGE_BLOCKS) * 256 + threadIdx.x;
        for (int t = tid0; t < 2 * N_EDGES; t += gsz)
            out[N_NODES * OUT_C + t] = (float)ei[t];
        float4*       dst4 = (float4*)(out + N_NODES * OUT_C + 2 * N_EDGES);
        const float4* src4 = (const float4*)ea;
        for (int t = tid0; t < N_EDGES * 2; t += gsz)
            dst4[t] = src4[t];
        return;
    }

    const int e   = blockIdx.x * 32 + (threadIdx.x >> 3);   // edge id
    const int sub = threadIdx.x & 7;                        // lane within edge

    const int src = __ldg(&ei[e]);
    const int dst = __ldg(&ei[N_EDGES + e]);

    // coefficients for this lane's two f-blocks
    const int f0 = sub >> 1;
    const float c0 = __ldg(&ea[e * EDGE_F + f0]);
    const float c1 = __ldg(&ea[e * EDGE_F + 4 + f0]);

    const uint4* yrow = g_yh + src * YSTRIDE;
    uint4 v0 = yrow[sub];          // block j = sub        (f = sub>>1, h = sub&1)
    uint4 v1 = yrow[8 + sub];      // block j = 8+sub      (f = 4+(sub>>1), h = sub&1)

    float acc[8];
    if (sub < 2) {                 // bias block j = 16+sub (f = 8, coef 1)
        uint4 v2 = yrow[16 + sub];
        const __half2* hv = (const __half2*)&v2;
        #pragma unroll
        for (int j = 0; j < 4; j++) {
            float2 p = __half22float2(hv[j]);
            acc[2*j] = p.x; acc[2*j+1] = p.y;
        }
    } else {
        #pragma unroll
        for (int o = 0; o < 8; o++) acc[o] = 0.f;
    }

    {
        const __half2* hv = (const __half2*)&v0;
        #pragma unroll
        for (int j = 0; j < 4; j++) {
            float2 p = __half22float2(hv[j]);
            acc[2*j]   += c0 * p.x;
            acc[2*j+1] += c0 * p.y;
        }
    }
    {
        const __half2* hv = (const __half2*)&v1;
        #pragma unroll
        for (int j = 0; j < 4; j++) {
            float2 p = __half22float2(hv[j]);
            acc[2*j]   += c1 * p.x;
            acc[2*j+1] += c1 * p.y;
        }
    }

    // reduce across lanes of same h-parity: {0,2,4,6} -> h=0, {1,3,5,7} -> h=1
    #pragma unroll
    for (int o = 0; o < 8; o++) acc[o] += __shfl_xor_sync(0xffffffffu, acc[o], 2);
    #pragma unroll
    for (int o = 0; o < 8; o++) acc[o] += __shfl_xor_sync(0xffffffffu, acc[o], 4);

    // 4 lanes/edge scatter one red.v4 each into the 64B-aligned dst row:
    //   sub0 -> out[dst][0:4]  (acc[0:4], h=0)
    //   sub1 -> out[dst][8:12] (acc[0:4], h=1)
    //   sub2 -> out[dst][4:8]  (acc[4:8], h=0)
    //   sub3 -> out[dst][12:16](acc[4:8], h=1)
    if (sub < 4) {
        const int  off = (sub & 1) * 8 + (sub >> 1) * 4;
        float* o = out + dst * OUT_C + off;
        float r0, r1, r2, r3;
        if (sub >= 2) { r0 = acc[4]; r1 = acc[5]; r2 = acc[6]; r3 = acc[7]; }
        else          { r0 = acc[0]; r1 = acc[1]; r2 = acc[2]; r3 = acc[3]; }
        asm volatile("red.global.add.v4.f32 [%0], {%1, %2, %3, %4};"
                     :: "l"(o), "f"(r0), "f"(r1), "f"(r2), "f"(r3)
                     : "memory");
    }
}

extern "C" void kernel_launch(void* const* d_in, const int* in_sizes, int n_in,
                              void* d_out, int out_size)
{
    const float* x     = (const float*)d_in[0];
    const int*   ei    = (const int*)  d_in[1];
    const float* ea    = (const float*)d_in[2];
    const float* w_nn  = (const float*)d_in[3];
    const float* b_nn  = (const float*)d_in[4];
    const float* root  = (const float*)d_in[5];
    const float* bias  = (const float*)d_in[6];
    float* out = (float*)d_out;

    node_kernel<<<1024, 256>>>(x, w_nn, b_nn, root, bias, out);
    edge_kernel<<<EDGE_BLOCKS + ECHO_BLOCKS, 256>>>(ei, ea, out);
}

// round 5
// speedup vs baseline: 1.0672x; 1.0672x over previous
#include <cuda_runtime.h>
#include <cuda_fp16.h>

#define N_NODES 50000
#define N_EDGES 800000
#define IN_C    16
#define OUT_C   16
#define EDGE_F  8

// y table in fp16: per node 9 blocks (8 edge-feature + 1 bias) x 16 outputs,
// = 18 uint4, PADDED to 24 uint4 (384 B = 3 cache lines, 128B-aligned).
// slot j = f*2 + h  (f = feature block, h = output half, uint4 units)
#define YSTRIDE 24

__device__ __align__(128) uint4 g_yh[N_NODES * YSTRIDE];   // 19.2 MB

// ---------------------------------------------------------------------------
// Kernel A: per-node precompute (fp16 y table, fp32 root-term init of out)
//          + echo streaming (edge_index as float, edge_attr copy).
// ---------------------------------------------------------------------------
__global__ void node_kernel(const float* __restrict__ x,
                            const int*   __restrict__ ei,
                            const float* __restrict__ ea,
                            const float* __restrict__ w_nn,
                            const float* __restrict__ b_nn,
                            const float* __restrict__ root,
                            const float* __restrict__ bias,
                            float* __restrict__ out,
                            int echo)
{
    __shared__ float Wsh[9 * 256];      // [f][i*16+o], f==8 holds b_nn
    __shared__ float Rsh[256 + 16];     // root [i][o] + bias[o]

    for (int t = threadIdx.x; t < 2048; t += blockDim.x) Wsh[t] = w_nn[t];
    for (int t = threadIdx.x; t < 256;  t += blockDim.x) Wsh[2048 + t] = b_nn[t];
    for (int t = threadIdx.x; t < 256;  t += blockDim.x) Rsh[t] = root[t];
    for (int t = threadIdx.x; t < 16;   t += blockDim.x) Rsh[256 + t] = bias[t];
    __syncthreads();

    const int gsz  = gridDim.x * blockDim.x;
    const int tid0 = blockIdx.x * blockDim.x + threadIdx.x;

    // ---- y precompute: thread = (node, output-half). 9 f-blocks each. ----
    for (int t = tid0; t < N_NODES * 2; t += gsz) {
        int n = t >> 1;
        int h = t & 1;                 // outputs h*8 .. h*8+7

        const float4* xr = (const float4*)(x + n * IN_C);
        float xv[16];
        #pragma unroll
        for (int ii = 0; ii < 4; ii++) {
            float4 xx = xr[ii];
            xv[4*ii+0] = xx.x; xv[4*ii+1] = xx.y; xv[4*ii+2] = xx.z; xv[4*ii+3] = xx.w;
        }

        #pragma unroll
        for (int f = 0; f < 9; f++) {
            const float* wb = &Wsh[f * 256 + h * 8];
            float acc[8];
            #pragma unroll
            for (int o = 0; o < 8; o++) acc[o] = 0.f;
            #pragma unroll
            for (int i = 0; i < 16; i++) {
                float xi = xv[i];
                #pragma unroll
                for (int o = 0; o < 8; o++) acc[o] += xi * wb[i * 16 + o];
            }
            __half2 hv[4];
            #pragma unroll
            for (int j = 0; j < 4; j++)
                hv[j] = __floats2half2_rn(acc[2*j], acc[2*j+1]);
            g_yh[n * YSTRIDE + f * 2 + h] = *(const uint4*)hv;
        }
    }

    // ---- root term init: out[n][oq*4..+3] = bias + x[n] @ root ----
    for (int t = tid0; t < N_NODES * 4; t += gsz) {
        int n  = t >> 2;
        int oq = t & 3;

        const float4* xr = (const float4*)(x + n * IN_C);
        float xv[16];
        #pragma unroll
        for (int ii = 0; ii < 4; ii++) {
            float4 xx = xr[ii];
            xv[4*ii+0] = xx.x; xv[4*ii+1] = xx.y; xv[4*ii+2] = xx.z; xv[4*ii+3] = xx.w;
        }

        float4 acc = *(const float4*)&Rsh[256 + oq * 4];
        #pragma unroll
        for (int i = 0; i < 16; i++) {
            float xi = xv[i];
            const float4 r = *(const float4*)&Rsh[i * 16 + oq * 4];
            acc.x += xi * r.x; acc.y += xi * r.y; acc.z += xi * r.z; acc.w += xi * r.w;
        }
        ((float4*)out)[t] = acc;
    }

    // ---- echoes (streaming, DRAM-bound) ----
    if (echo & 1) {
        for (int t = tid0; t < 2 * N_EDGES; t += gsz)
            out[N_NODES * OUT_C + t] = (float)ei[t];
    }
    if (echo & 2) {
        float4*       dst4 = (float4*)(out + N_NODES * OUT_C + 2 * N_EDGES);
        const float4* src4 = (const float4*)ea;
        for (int t = tid0; t < N_EDGES * 2; t += gsz)
            dst4[t] = src4[t];
    }
}

// ---------------------------------------------------------------------------
// Kernel B: 4 lanes per edge (8 edges/warp).
//   Lane sub owns slots {sub, sub+4, sub+8, sub+12}: h = sub&1 output half,
//   f-parity = sub>>1. One shfl_xor(2) round combines the two f-parities;
//   lanes 0,1 fire 2 red.v4 each into the dst row.
//   Gather = 5 LDG.128 covering the 384 B padded row in aligned 64 B chunks.
// ---------------------------------------------------------------------------
__global__ void edge_kernel(const int*   __restrict__ ei,
                            const float* __restrict__ ea,
                            float* __restrict__ out)
{
    const int g   = blockIdx.x * blockDim.x + threadIdx.x;
    const int e   = g >> 2;                 // edge id (exact: grid*256/4 == N_EDGES)
    const int sub = g & 3;
    const int s2  = sub >> 1;               // f-parity this lane handles

    const int src = __ldg(&ei[e]);
    const int dst = __ldg(&ei[N_EDGES + e]);

    // edge coefficients: lane needs f = s2, s2+2, s2+4, s2+6
    const float4* ea4 = (const float4*)ea;
    const float4 a0 = ea4[2 * e];
    const float4 a1 = ea4[2 * e + 1];
    const float c0 = s2 ? a0.y : a0.x;
    const float c1 = s2 ? a0.w : a0.z;
    const float c2 = s2 ? a1.y : a1.x;
    const float c3 = s2 ? a1.w : a1.z;

    const uint4* yrow = g_yh + src * YSTRIDE;
    const uint4 v0 = yrow[sub];
    const uint4 v1 = yrow[sub + 4];
    const uint4 v2 = yrow[sub + 8];
    const uint4 v3 = yrow[sub + 12];

    float acc[8];
    if (sub < 2) {   // bias block slot 16+sub (f=8, h=sub), coefficient 1
        const uint4 vb = yrow[16 + sub];
        const __half2* hv = (const __half2*)&vb;
        #pragma unroll
        for (int j = 0; j < 4; j++) {
            float2 p = __half22float2(hv[j]);
            acc[2*j] = p.x; acc[2*j+1] = p.y;
        }
    } else {
        #pragma unroll
        for (int o = 0; o < 8; o++) acc[o] = 0.f;
    }

    #pragma unroll
    for (int b = 0; b < 4; b++) {
        const uint4  v  = (b == 0) ? v0 : (b == 1) ? v1 : (b == 2) ? v2 : v3;
        const float  cf = (b == 0) ? c0 : (b == 1) ? c1 : (b == 2) ? c2 : c3;
        const __half2* hv = (const __half2*)&v;
        #pragma unroll
        for (int j = 0; j < 4; j++) {
            float2 p = __half22float2(hv[j]);
            acc[2*j]   += cf * p.x;
            acc[2*j+1] += cf * p.y;
        }
    }

    // combine the two f-parities: lane pairs (0,2) and (1,3)
    #pragma unroll
    for (int o = 0; o < 8; o++)
        acc[o] += __shfl_xor_sync(0xffffffffu, acc[o], 2);

    // lanes 0,1 hold the full output half h=sub: 2 red.v4 each
    if (sub < 2) {
        float* o = out + dst * OUT_C + sub * 8;
        asm volatile("red.global.add.v4.f32 [%0], {%1, %2, %3, %4};"
                     :: "l"(o),     "f"(acc[0]), "f"(acc[1]), "f"(acc[2]), "f"(acc[3])
                     : "memory");
        asm volatile("red.global.add.v4.f32 [%0], {%1, %2, %3, %4};"
                     :: "l"(o + 4), "f"(acc[4]), "f"(acc[5]), "f"(acc[6]), "f"(acc[7])
                     : "memory");
    }
}

extern "C" void kernel_launch(void* const* d_in, const int* in_sizes, int n_in,
                              void* d_out, int out_size)
{
    const float* x     = (const float*)d_in[0];
    const int*   ei    = (const int*)  d_in[1];
    const float* ea    = (const float*)d_in[2];
    const float* w_nn  = (const float*)d_in[3];
    const float* b_nn  = (const float*)d_in[4];
    const float* root  = (const float*)d_in[5];
    const float* bias  = (const float*)d_in[6];
    float* out = (float*)d_out;

    int echo = 0;
    if (out_size >= N_NODES * OUT_C + 2 * N_EDGES)                        echo |= 1;
    if (out_size >= N_NODES * OUT_C + 2 * N_EDGES + N_EDGES * EDGE_F)     echo |= 2;

    node_kernel<<<2048, 256>>>(x, ei, ea, w_nn, b_nn, root, bias, out, echo);
    edge_kernel<<<(N_EDGES * 4) / 256, 256>>>(ei, ea, out);
}